// round 15
// baseline (speedup 1.0000x reference)
#include <cuda_runtime.h>
#include <cuda_fp16.h>
#include <math.h>
#include <stdint.h>

// ---------------- problem constants ----------------
#define BB   256
#define TT   512
#define HH   1024
#define NCTA 128
#define NTHR 512      // 16 warps = wmh(2) x wq(2) x ks(4)

// 128 CTAs = 32 mi (32 neurons) x 4 nb (64 batch); K split 4-way inside CTA.
// SMEM: A frags (W hi 64K | lo 64K fp16) | 8 group B bufs (2 x 4K) | red 24K
#define OFF_ALO 65536
#define OFF_B   131072
#define OFF_RED 196608
#define SMEM_SZ 221184

// ---------------- device globals ----------------
// h in fp16 B-frag order: [buf][nb][kk 64][oct 8][lane 32] uint2
__device__ __align__(16) uint2 g_hf[2][4][64][8][32];    // 1 MB
// per-octet publish flags: [nb][oct 8][row 64]
__device__ volatile int g_dw4[4][8][64];
__device__ volatile int g_flags[NCTA];                   // one-time init barrier

__device__ __forceinline__ uint32_t pack_hf(float x, float y) {
    __half2 v = __floats2half2_rn(x, y);
    return *reinterpret_cast<uint32_t*>(&v);
}
__device__ __forceinline__ unsigned short hbits(float x) {
    return __half_as_ushort(__float2half_rn(x));
}
__device__ __forceinline__ float hup(unsigned short u) {
    return __half2float(__ushort_as_half(u));
}
__device__ __forceinline__ void mma16816h(float* c, const uint32_t* a,
                                          const uint32_t* b) {
    asm volatile(
        "mma.sync.aligned.m16n8k16.row.col.f32.f16.f16.f32 "
        "{%0,%1,%2,%3}, {%4,%5,%6,%7}, {%8,%9}, {%0,%1,%2,%3};"
        : "+f"(c[0]), "+f"(c[1]), "+f"(c[2]), "+f"(c[3])
        : "r"(a[0]), "r"(a[1]), "r"(a[2]), "r"(a[3]), "r"(b[0]), "r"(b[1]));
}
__device__ __forceinline__ float ftanh(float x) {
    float e = __expf(2.f * x);
    return 1.f - __fdividef(2.f, e + 1.f);
}
__device__ __forceinline__ void ldvol4(int* r, const volatile int* p) {
    asm volatile("ld.volatile.global.v4.u32 {%0,%1,%2,%3}, [%4];"
                 : "=r"(r[0]), "=r"(r[1]), "=r"(r[2]), "=r"(r[3])
                 : "l"(p));
}

extern "C" __global__ void __launch_bounds__(NTHR, 1)
rnn_decoder_kernel(const float* __restrict__ init_in,   // [B,1]
                   const float* __restrict__ hidden0,   // [B,H]
                   const float* __restrict__ targets,   // [T,B,1]
                   const float* __restrict__ W_ih,      // [H,1]
                   const float* __restrict__ W_hh,      // [H,H]
                   const float* __restrict__ b_ih,      // [H]
                   const float* __restrict__ b_hh,      // [H]
                   const float* __restrict__ W_out,     // [1,H]
                   const float* __restrict__ b_out,     // [1]
                   float* __restrict__ out)             // [T,B,1]
{
    extern __shared__ __align__(16) char smem[];
    uint32_t sb;
    asm("{ .reg .u64 t; cvta.to.shared.u64 t, %1; cvt.u32.u64 %0, t; }"
        : "=r"(sb) : "l"(smem));

    const int tid  = threadIdx.x;
    const int cta  = blockIdx.x;
    const int wid  = tid >> 5;
    const int lane = tid & 31;
    const int g    = lane >> 2;
    const int tq   = lane & 3;
    const int wmh  = wid & 1;            // M half (16 rows)
    const int grp  = wid >> 1;           // 0..7
    const int wq   = grp >> 2;           // col half (32 cols)
    const int ks   = grp & 3;            // K slice (16 kk)
    const int oct  = 4 * wq + ks;        // owned output octet

    const int mi  = cta >> 2;            // 0..31
    const int nb  = cta & 3;             // 0..3
    const int m0  = mi * 32;
    const int bb0 = nb * 64;

    const int base_g = g_flags[cta];
    const int base_d = g_dw4[nb][oct][mi * 2 + wmh];

    // ---- one-time: A fragments (W hi+lo fp16) in exact mma lane order ----
    {
        const int r0 = m0 + wmh * 16 + g;
        const int r1 = r0 + 8;
        for (int jj = 0; jj < 8; jj++) {
            const int kk = grp + 8 * jj;                 // 0..63
            const int c  = kk * 16 + 2 * tq;
            float w00 = W_hh[(size_t)r0 * HH + c];
            float w01 = W_hh[(size_t)r0 * HH + c + 1];
            float w04 = W_hh[(size_t)r0 * HH + c + 8];
            float w05 = W_hh[(size_t)r0 * HH + c + 9];
            float w10 = W_hh[(size_t)r1 * HH + c];
            float w11 = W_hh[(size_t)r1 * HH + c + 1];
            float w14 = W_hh[(size_t)r1 * HH + c + 8];
            float w15 = W_hh[(size_t)r1 * HH + c + 9];
            uint4 hi, lo;
            hi.x = pack_hf(w00, w01);
            hi.y = pack_hf(w10, w11);
            hi.z = pack_hf(w04, w05);
            hi.w = pack_hf(w14, w15);
            lo.x = pack_hf(w00 - hup(hbits(w00)), w01 - hup(hbits(w01)));
            lo.y = pack_hf(w10 - hup(hbits(w10)), w11 - hup(hbits(w11)));
            lo.z = pack_hf(w04 - hup(hbits(w04)), w05 - hup(hbits(w05)));
            lo.w = pack_hf(w14 - hup(hbits(w14)), w15 - hup(hbits(w15)));
            const int ob = (wmh * 64 + kk) * 512 + lane * 16;
            *reinterpret_cast<uint4*>(smem + ob)           = hi;
            *reinterpret_cast<uint4*>(smem + OFF_ALO + ob) = lo;
        }
    }

    // ---- one-time: publish h0 slice into g_hf[1] ----
    {
        const int pwmh = tid >> 8;
        const int poct = (tid >> 5) & 7;
        const int pln  = tid & 31;
        const int pcol = pln >> 2;
        const int pg   = (pln & 3) * 2;
        const int col  = bb0 + poct * 8 + pcol;
        const int rA   = m0 + pwmh * 16 + pg;
        float va = hidden0[(size_t)col * HH + rA];
        float vb = hidden0[(size_t)col * HH + rA + 1];
        float vc = hidden0[(size_t)col * HH + rA + 8];
        float vd = hidden0[(size_t)col * HH + rA + 9];
        uint2 u;
        u.x = (uint32_t)hbits(va) | ((uint32_t)hbits(vb) << 16);
        u.y = (uint32_t)hbits(vc) | ((uint32_t)hbits(vd) << 16);
        g_hf[1][nb][mi * 2 + pwmh][poct][pcol * 4 + (pg >> 1)] = u;
    }
    // ---- one-time: out init to b_out ----
    {
        const float bo = b_out[0];
        out[(size_t)cta * 1024 + tid]       = bo;
        out[(size_t)cta * 1024 + 512 + tid] = bo;
    }

    // epilogue constants for my 2 rows
    const int r0g = m0 + wmh * 16 + g, r8g = r0g + 8;
    const float bias_g = b_ih[r0g] + b_hh[r0g], bias_8 = b_ih[r8g] + b_hh[r8g];
    const float wih_g = W_ih[r0g], wih_8 = W_ih[r8g];
    const float wout_g = W_out[r0g], wout_8 = W_out[r8g];

    // ---- one-time grid barrier ----
    __threadfence();
    __syncthreads();
    if (tid == 0) g_flags[cta] = base_g + 1;
    if (tid < 32) {
        const int tgt = base_g + 1;
        bool ok;
        do {
            int a = g_flags[tid];
            int b = g_flags[tid + 32];
            int c = g_flags[tid + 64];
            int d = g_flags[tid + 96];
            ok = (a >= tgt) & (b >= tgt) & (c >= tgt) & (d >= tgt);
        } while (!__all_sync(0xffffffffu, ok));
        __threadfence();
    }
    __syncthreads();

    const int barid = 1 + grp;           // per-(wq,ks) group bar (64 thr)
    const int redid = 9 + wmh * 2 + wq;  // per-(wmh,wq) reduce bar (128 thr)
    // red region per (wmh,wq): [dest 4][src 3][e 4][lane 32] = 1536 floats
    float* redf = reinterpret_cast<float*>(smem + OFF_RED) +
                  (wmh * 2 + wq) * 1536;

#pragma unroll 1
    for (int t = 0; t < TT; t++) {
        const int rbuf = (t + 1) & 1, wbuf = t & 1;
        const char* srcB = (const char*)&g_hf[rbuf][nb][0][0][0];
        const int tgt = base_d + t;

        // x for my 2 owned cols
        const float* xsrc = (t == 0) ? init_in : (targets + (size_t)(t - 1) * BB);
        const float xv0 = __ldg(&xsrc[bb0 + oct * 8 + 2 * tq]);
        const float xv1 = __ldg(&xsrc[bb0 + oct * 8 + 2 * tq + 1]);

        // poll chunk c: rows 16ks+4c..+3 of octets 4wq..4wq+3 (16 flags)
        auto poll = [&](int c) {
            const int rbase = 16 * ks + 4 * c;
            int r[16];
            bool ok;
            do {
                ldvol4(r,      &g_dw4[nb][4 * wq][rbase]);
                ldvol4(r + 4,  &g_dw4[nb][4 * wq + 1][rbase]);
                ldvol4(r + 8,  &g_dw4[nb][4 * wq + 2][rbase]);
                ldvol4(r + 12, &g_dw4[nb][4 * wq + 3][rbase]);
                ok = true;
#pragma unroll
                for (int i = 0; i < 16; i++) ok &= (r[i] >= tgt);
            } while (!ok);
            __threadfence();
        };
        // cp.async chunk j (4 KB: 4 kk x 4 oct) into parity p
        auto cpchunk = [&](int j, int p) {
            const uint32_t dst = sb + OFF_B + grp * 8192 + p * 4096;
#pragma unroll
            for (int i = 0; i < 8; i++) {
                const int flat = i * 32 + lane;          // 0..255
                const int seg  = flat >> 4;              // 0..15
                const int kkL  = seg >> 2;
                const int oc   = seg & 3;
                const int inr  = (flat & 15) * 16;
                asm volatile("cp.async.cg.shared.global [%0], [%1], 16;"
                             :: "r"(dst + seg * 256 + inr),
                                "l"(srcB + (size_t)(((16 * ks + 4 * j + kkL) * 8 +
                                                    4 * wq + oc) * 256 + inr)));
            }
            asm volatile("cp.async.commit_group;" ::: "memory");
        };

        if (wmh == 0) {
            poll(0); cpchunk(0, 0);
            asm volatile("cp.async.wait_group 0;" ::: "memory");
        } else {
            poll(1);
        }

        float accH[4][4], accL[4][4];
#pragma unroll
        for (int o = 0; o < 4; o++)
#pragma unroll
            for (int e = 0; e < 4; e++) { accH[o][e] = 0.f; accL[o][e] = 0.f; }

#pragma unroll 1
        for (int j = 0; j < 4; j++) {
            asm volatile("bar.sync %0, 64;" :: "r"(barid) : "memory");
            if (j < 3 && wmh == 0) cpchunk(j + 1, (j + 1) & 1);
            if (j < 2 && wmh == 1) poll(j + 2);

            const int bB = OFF_B + grp * 8192 + (j & 1) * 4096 + lane * 8;
#pragma unroll
            for (int k4 = 0; k4 < 4; k4++) {
                const int kk = 16 * ks + 4 * j + k4;
                const int ab = (wmh * 64 + kk) * 512 + lane * 16;
                uint4 Ah = *reinterpret_cast<const uint4*>(smem + ab);
                uint4 Al = *reinterpret_cast<const uint4*>(smem + OFF_ALO + ab);
#pragma unroll
                for (int o = 0; o < 4; o++) {
                    uint2 V = *reinterpret_cast<const uint2*>(
                        smem + bB + (k4 * 4 + o) * 256);
                    uint32_t Bf[2] = {V.x, V.y};
                    mma16816h(accH[o], &Ah.x, Bf);
                    mma16816h(accL[o], &Al.x, Bf);
                }
            }
            if (j < 3 && wmh == 0)
                asm volatile("cp.async.wait_group 0;" ::: "memory");
        }

        // ---- cross-ks exchange: warp ks owns dest o = ks ----
        float s[4][4];
#pragma unroll
        for (int o = 0; o < 4; o++)
#pragma unroll
            for (int e = 0; e < 4; e++) s[o][e] = accH[o][e] + accL[o][e];

        asm volatile("bar.sync %0, 128;" :: "r"(redid) : "memory");   // barA
#pragma unroll
        for (int o = 0; o < 4; o++) {
            if (o != ks) {
                const int slot = (ks > o) ? (ks - 1) : ks;
#pragma unroll
                for (int e = 0; e < 4; e++)
                    redf[o * 384 + slot * 128 + e * 32 + lane] = s[o][e];
            }
        }
        asm volatile("bar.sync %0, 128;" :: "r"(redid) : "memory");   // barB

        float so[4];
#pragma unroll
        for (int e = 0; e < 4; e++)
            so[e] = s[ks][e] + redf[ks * 384 + e * 32 + lane] +
                    redf[ks * 384 + 128 + e * 32 + lane] +
                    redf[ks * 384 + 256 + e * 32 + lane];

        // ---- distributed epilogue: tanh, publish, flag, then y ----
        float hg0 = ftanh(so[0] + fmaf(xv0, wih_g, bias_g));
        float hg1 = ftanh(so[1] + fmaf(xv1, wih_g, bias_g));
        float h80 = ftanh(so[2] + fmaf(xv0, wih_8, bias_8));
        float h81 = ftanh(so[3] + fmaf(xv1, wih_8, bias_8));

        const float hgv[2] = {hg0, hg1};
        const float h8v[2] = {h80, h81};
#pragma unroll
        for (int c = 0; c < 2; c++) {
            uint32_t P1 = (uint32_t)hbits(hgv[c]) | ((uint32_t)hbits(h8v[c]) << 16);
            uint32_t q1 = __shfl_xor_sync(0xffffffffu, P1, 4);
            if ((g & 1) == 0) {
                uint2 u;
                u.x = __byte_perm(P1, q1, 0x5410);   // slot0: rows g,g+1
                u.y = __byte_perm(P1, q1, 0x7632);   // slot1: rows g+8,g+9
                g_hf[wbuf][nb][mi * 2 + wmh][oct][(2 * tq + c) * 4 + (g >> 1)] = u;
            }
        }
        __threadfence();
        __syncwarp();
        if (lane == 0) g_dw4[nb][oct][mi * 2 + wmh] = base_d + t + 1;

        // y partials after the flag (off the recurrence critical path)
        float yp0 = hg0 * wout_g + h80 * wout_8;
        float yp1 = hg1 * wout_g + h81 * wout_8;
#pragma unroll
        for (int off = 4; off < 32; off <<= 1) {
            yp0 += __shfl_xor_sync(0xffffffffu, yp0, off);
            yp1 += __shfl_xor_sync(0xffffffffu, yp1, off);
        }
        if (lane < 4) {
            atomicAdd(&out[(size_t)t * BB + bb0 + oct * 8 + 2 * lane],     yp0);
            atomicAdd(&out[(size_t)t * BB + bb0 + oct * 8 + 2 * lane + 1], yp1);
        }
    }
}

extern "C" void kernel_launch(void* const* d_in, const int* in_sizes, int n_in,
                              void* d_out, int out_size) {
    const float* init_in = (const float*)d_in[0];
    const float* hidden0 = (const float*)d_in[1];
    const float* targets = (const float*)d_in[2];
    const float* W_ih    = (const float*)d_in[3];
    const float* W_hh    = (const float*)d_in[4];
    const float* b_ih    = (const float*)d_in[5];
    const float* b_hh    = (const float*)d_in[6];
    const float* W_out   = (const float*)d_in[7];
    const float* b_out   = (const float*)d_in[8];
    float* out = (float*)d_out;

    cudaFuncSetAttribute(rnn_decoder_kernel,
                         cudaFuncAttributeMaxDynamicSharedMemorySize, SMEM_SZ);
    rnn_decoder_kernel<<<NCTA, NTHR, SMEM_SZ>>>(init_in, hidden0, targets, W_ih,
                                                W_hh, b_ih, b_hh, W_out, b_out,
                                                out);
}

// round 16
// speedup vs baseline: 1.0283x; 1.0283x over previous
#include <cuda_runtime.h>
#include <cuda_fp16.h>
#include <math.h>
#include <stdint.h>

// ---------------- problem constants ----------------
#define BB   256
#define TT   512
#define HH   1024
#define NCTA 128
#define NTHR 512      // 16 warps = wmh(2) x wq(2) x ks(4)

// 128 CTAs = 32 mi (32 neurons) x 4 nb (64 batch); K split 4-way inside CTA.
// SMEM: A frags (W hi 64K | lo 64K fp16) | 8 group B bufs (2 x 4K each) | red
#define OFF_ALO 65536
#define OFF_B   131072
#define OFF_RED 196608
#define SMEM_SZ 221184

// ---------------- device globals ----------------
// h in fp16 B-frag order: [buf][nb][kk 64][oct 8][lane 32] uint2
__device__ __align__(16) uint2 g_hf[2][4][64][8][32];    // 1 MB
// publish flags: [nb][wq][kk-rowgroup 64]
__device__ volatile int g_dw3[4][2][64];
__device__ volatile int g_flags[NCTA];                   // one-time init barrier

__device__ __forceinline__ uint32_t pack_hf(float x, float y) {
    __half2 v = __floats2half2_rn(x, y);
    return *reinterpret_cast<uint32_t*>(&v);
}
__device__ __forceinline__ unsigned short hbits(float x) {
    return __half_as_ushort(__float2half_rn(x));
}
__device__ __forceinline__ float hup(unsigned short u) {
    return __half2float(__ushort_as_half(u));
}
__device__ __forceinline__ void mma16816h(float* c, const uint32_t* a,
                                          const uint32_t* b) {
    asm volatile(
        "mma.sync.aligned.m16n8k16.row.col.f32.f16.f16.f32 "
        "{%0,%1,%2,%3}, {%4,%5,%6,%7}, {%8,%9}, {%0,%1,%2,%3};"
        : "+f"(c[0]), "+f"(c[1]), "+f"(c[2]), "+f"(c[3])
        : "r"(a[0]), "r"(a[1]), "r"(a[2]), "r"(a[3]), "r"(b[0]), "r"(b[1]));
}
__device__ __forceinline__ float ftanh(float x) {
    float e = __expf(2.f * x);
    return 1.f - __fdividef(2.f, e + 1.f);
}
__device__ __forceinline__ void ldvol4(int* r, const volatile int* p) {
    asm volatile("ld.volatile.global.v4.u32 {%0,%1,%2,%3}, [%4];"
                 : "=r"(r[0]), "=r"(r[1]), "=r"(r[2]), "=r"(r[3])
                 : "l"(p));
}

extern "C" __global__ void __launch_bounds__(NTHR, 1)
rnn_decoder_kernel(const float* __restrict__ init_in,   // [B,1]
                   const float* __restrict__ hidden0,   // [B,H]
                   const float* __restrict__ targets,   // [T,B,1]
                   const float* __restrict__ W_ih,      // [H,1]
                   const float* __restrict__ W_hh,      // [H,H]
                   const float* __restrict__ b_ih,      // [H]
                   const float* __restrict__ b_hh,      // [H]
                   const float* __restrict__ W_out,     // [1,H]
                   const float* __restrict__ b_out,     // [1]
                   float* __restrict__ out)             // [T,B,1]
{
    extern __shared__ __align__(16) char smem[];
    uint32_t sb;
    asm("{ .reg .u64 t; cvta.to.shared.u64 t, %1; cvt.u32.u64 %0, t; }"
        : "=r"(sb) : "l"(smem));

    const int tid  = threadIdx.x;
    const int cta  = blockIdx.x;
    const int wid  = tid >> 5;
    const int lane = tid & 31;
    const int g    = lane >> 2;
    const int tq   = lane & 3;
    const int wmh  = wid & 1;            // M half (16 rows)
    const int grp  = wid >> 1;           // 0..7
    const int wq   = grp >> 2;           // col half (32 cols)
    const int ks   = grp & 3;            // K slice (256 n's = 16 kk)

    const int mi  = cta >> 2;            // 0..31
    const int nb  = cta & 3;             // 0..3
    const int m0  = mi * 32;
    const int bb0 = nb * 64;

    const int base_g = g_flags[cta];
    const int base_d = g_dw3[nb][wq][mi * 2 + wmh];

    // ---- one-time: A fragments (W hi+lo fp16) in exact mma lane order ----
    {
        const int r0 = m0 + wmh * 16 + g;
        const int r1 = r0 + 8;
        for (int jj = 0; jj < 8; jj++) {
            const int kk = grp + 8 * jj;                 // 0..63
            const int c  = kk * 16 + 2 * tq;
            float w00 = W_hh[(size_t)r0 * HH + c];
            float w01 = W_hh[(size_t)r0 * HH + c + 1];
            float w04 = W_hh[(size_t)r0 * HH + c + 8];
            float w05 = W_hh[(size_t)r0 * HH + c + 9];
            float w10 = W_hh[(size_t)r1 * HH + c];
            float w11 = W_hh[(size_t)r1 * HH + c + 1];
            float w14 = W_hh[(size_t)r1 * HH + c + 8];
            float w15 = W_hh[(size_t)r1 * HH + c + 9];
            uint4 hi, lo;
            hi.x = pack_hf(w00, w01);
            hi.y = pack_hf(w10, w11);
            hi.z = pack_hf(w04, w05);
            hi.w = pack_hf(w14, w15);
            lo.x = pack_hf(w00 - hup(hbits(w00)), w01 - hup(hbits(w01)));
            lo.y = pack_hf(w10 - hup(hbits(w10)), w11 - hup(hbits(w11)));
            lo.z = pack_hf(w04 - hup(hbits(w04)), w05 - hup(hbits(w05)));
            lo.w = pack_hf(w14 - hup(hbits(w14)), w15 - hup(hbits(w15)));
            const int ob = (wmh * 64 + kk) * 512 + lane * 16;
            *reinterpret_cast<uint4*>(smem + ob)           = hi;
            *reinterpret_cast<uint4*>(smem + OFF_ALO + ob) = lo;
        }
    }

    // ---- one-time: publish h0 slice into g_hf[1] ----
    {
        const int pwmh = tid >> 8;
        const int poct = (tid >> 5) & 7;
        const int pln  = tid & 31;
        const int pcol = pln >> 2;
        const int pg   = (pln & 3) * 2;
        const int col  = bb0 + poct * 8 + pcol;
        const int rA   = m0 + pwmh * 16 + pg;
        float va = hidden0[(size_t)col * HH + rA];
        float vb = hidden0[(size_t)col * HH + rA + 1];
        float vc = hidden0[(size_t)col * HH + rA + 8];
        float vd = hidden0[(size_t)col * HH + rA + 9];
        uint2 u;
        u.x = (uint32_t)hbits(va) | ((uint32_t)hbits(vb) << 16);
        u.y = (uint32_t)hbits(vc) | ((uint32_t)hbits(vd) << 16);
        g_hf[1][nb][mi * 2 + pwmh][poct][pcol * 4 + (pg >> 1)] = u;
    }
    // ---- one-time: out init to b_out ----
    {
        const float bo = b_out[0];
        out[(size_t)cta * 1024 + tid]       = bo;
        out[(size_t)cta * 1024 + 512 + tid] = bo;
    }

    // epilogue constants for my 2 rows
    const int r0g = m0 + wmh * 16 + g, r8g = r0g + 8;
    const float bias_g = b_ih[r0g] + b_hh[r0g], bias_8 = b_ih[r8g] + b_hh[r8g];
    const float wih_g = W_ih[r0g], wih_8 = W_ih[r8g];
    const float wout_g = W_out[r0g], wout_8 = W_out[r8g];

    // ---- one-time grid barrier ----
    __threadfence();
    __syncthreads();
    if (tid == 0) g_flags[cta] = base_g + 1;
    if (tid < 32) {
        const int tgt = base_g + 1;
        bool ok;
        do {
            int a = g_flags[tid];
            int b = g_flags[tid + 32];
            int c = g_flags[tid + 64];
            int d = g_flags[tid + 96];
            ok = (a >= tgt) & (b >= tgt) & (c >= tgt) & (d >= tgt);
        } while (!__all_sync(0xffffffffu, ok));
        __threadfence();
    }
    __syncthreads();

    const int barid = 1 + grp;           // per-(wq,ks) group bar (64 thr)
    const int redid = 9 + wmh * 2 + wq;  // per-(wmh,wq) reduce bar (128 thr)
    float* redf = reinterpret_cast<float*>(smem + OFF_RED) +
                  (wmh * 2 + wq) * 1536;                 // 3 slices x 512 floats

#pragma unroll 1
    for (int t = 0; t < TT; t++) {
        const int rbuf = (t + 1) & 1, wbuf = t & 1;
        const char* srcB = (const char*)&g_hf[rbuf][nb][0][0][0];
        const int tgt = base_d + t;

        // x for ks0 epilogue cols (8 per lane)
        float xv[4][2];
        if (ks == 0) {
            const float* xsrc = (t == 0) ? init_in
                                         : (targets + (size_t)(t - 1) * BB);
#pragma unroll
            for (int o = 0; o < 4; o++) {
                xv[o][0] = __ldg(&xsrc[bb0 + wq * 32 + o * 8 + 2 * tq]);
                xv[o][1] = __ldg(&xsrc[bb0 + wq * 32 + o * 8 + 2 * tq + 1]);
            }
        }

        // poll chunk c: 4 contiguous flags [nb][wq][16ks+4c..]
        auto poll = [&](int c) {
            const volatile int* f = &g_dw3[nb][wq][16 * ks + 4 * c];
            int r[4];
            bool ok;
            do {
                ldvol4(r, f);
                ok = (r[0] >= tgt) & (r[1] >= tgt) & (r[2] >= tgt) & (r[3] >= tgt);
            } while (!ok);
            __threadfence();
        };
        // cp.async chunk j (4 KB: 4 kk x 4 oct) into parity p; half = 2 KB
        auto cphalf = [&](int j, int p, int half) {
            const uint32_t dst = sb + OFF_B + grp * 8192 + p * 4096;
#pragma unroll
            for (int i = 0; i < 4; i++) {
                const int flat = (half * 4 + i) * 32 + lane;   // 0..255
                const int seg  = flat >> 4;              // 0..15
                const int kkL  = seg >> 2;
                const int oct  = seg & 3;
                const int inr  = (flat & 15) * 16;
                asm volatile("cp.async.cg.shared.global [%0], [%1], 16;"
                             :: "r"(dst + seg * 256 + inr),
                                "l"(srcB + (size_t)(((16 * ks + 4 * j + kkL) * 8 +
                                                    4 * wq + oct) * 256 + inr)));
            }
            asm volatile("cp.async.commit_group;" ::: "memory");
        };

        // prologue: wmh0 readies chunk 0 (both halves); wmh1 verifies chunk 1
        if (wmh == 0) {
            poll(0); cphalf(0, 0, 0); cphalf(0, 0, 1);
            asm volatile("cp.async.wait_group 0;" ::: "memory");
        } else {
            poll(1);
        }

        float accH[4][4], accL[4][4];
#pragma unroll
        for (int o = 0; o < 4; o++)
#pragma unroll
            for (int e = 0; e < 4; e++) { accH[o][e] = 0.f; accL[o][e] = 0.f; }

#pragma unroll 1
        for (int j = 0; j < 4; j++) {
            asm volatile("bar.sync %0, 64;" :: "r"(barid) : "memory");
            // both warps cp their half of chunk j+1 (flags verified by wmh1
            // one iteration ago; ordered by the bar above)
            if (j < 3) cphalf(j + 1, (j + 1) & 1, wmh);
            // wmh1: verify flags for chunk j+2 (lookahead)
            if (j < 2 && wmh == 1) poll(j + 2);

            const int bB = OFF_B + grp * 8192 + (j & 1) * 4096 + lane * 8;
#pragma unroll
            for (int k4 = 0; k4 < 4; k4++) {
                const int kk = 16 * ks + 4 * j + k4;
                const int ab = (wmh * 64 + kk) * 512 + lane * 16;
                uint4 Ah = *reinterpret_cast<const uint4*>(smem + ab);
                uint4 Al = *reinterpret_cast<const uint4*>(smem + OFF_ALO + ab);
#pragma unroll
                for (int o = 0; o < 4; o++) {
                    uint2 V = *reinterpret_cast<const uint2*>(
                        smem + bB + (k4 * 4 + o) * 256);
                    uint32_t Bf[2] = {V.x, V.y};
                    mma16816h(accH[o], &Ah.x, Bf);
                    mma16816h(accL[o], &Al.x, Bf);
                }
            }
            if (j < 3)
                asm volatile("cp.async.wait_group 0;" ::: "memory");
        }

        // ---- cross-ks reduction ----
        float s[4][4];
#pragma unroll
        for (int o = 0; o < 4; o++)
#pragma unroll
            for (int e = 0; e < 4; e++) s[o][e] = accH[o][e] + accL[o][e];

        asm volatile("bar.sync %0, 128;" :: "r"(redid) : "memory");   // barA
        if (ks) {
            float* red = redf + (ks - 1) * 512;
#pragma unroll
            for (int f = 0; f < 16; f++) red[f * 32 + lane] = s[f >> 2][f & 3];
        }
        asm volatile("bar.sync %0, 128;" :: "r"(redid) : "memory");   // barB

        if (ks == 0) {
#pragma unroll
            for (int f = 0; f < 16; f++)
                s[f >> 2][f & 3] += redf[f * 32 + lane] +
                                    redf[512 + f * 32 + lane] +
                                    redf[1024 + f * 32 + lane];

            float hg[4][2], h8[4][2];
#pragma unroll
            for (int o = 0; o < 4; o++) {
                hg[o][0] = ftanh(s[o][0] + fmaf(xv[o][0], wih_g, bias_g));
                hg[o][1] = ftanh(s[o][1] + fmaf(xv[o][1], wih_g, bias_g));
                h8[o][0] = ftanh(s[o][2] + fmaf(xv[o][0], wih_8, bias_8));
                h8[o][1] = ftanh(s[o][3] + fmaf(xv[o][1], wih_8, bias_8));
            }
            // publish h' frags (even-g lanes)
#pragma unroll
            for (int o = 0; o < 4; o++)
#pragma unroll
                for (int c = 0; c < 2; c++) {
                    uint32_t P1 = (uint32_t)hbits(hg[o][c]) |
                                  ((uint32_t)hbits(h8[o][c]) << 16);
                    uint32_t q1 = __shfl_xor_sync(0xffffffffu, P1, 4);
                    if ((g & 1) == 0) {
                        uint2 u;
                        u.x = __byte_perm(P1, q1, 0x5410);
                        u.y = __byte_perm(P1, q1, 0x7632);
                        g_hf[wbuf][nb][mi * 2 + wmh][4 * wq + o]
                            [(2 * tq + c) * 4 + (g >> 1)] = u;
                    }
                }
            __threadfence();
            __syncwarp();
            if (lane == 0) g_dw3[nb][wq][mi * 2 + wmh] = base_d + t + 1;

            // y partials (off critical path)
            float yp[4][2];
#pragma unroll
            for (int o = 0; o < 4; o++)
#pragma unroll
                for (int c = 0; c < 2; c++)
                    yp[o][c] = hg[o][c] * wout_g + h8[o][c] * wout_8;
#pragma unroll
            for (int off = 4; off < 32; off <<= 1)
#pragma unroll
                for (int o = 0; o < 4; o++)
#pragma unroll
                    for (int c = 0; c < 2; c++)
                        yp[o][c] += __shfl_xor_sync(0xffffffffu, yp[o][c], off);
            if (lane < 4) {
#pragma unroll
                for (int o = 0; o < 4; o++)
#pragma unroll
                    for (int c = 0; c < 2; c++)
                        atomicAdd(&out[(size_t)t * BB + bb0 + wq * 32 + o * 8 +
                                       2 * lane + c], yp[o][c]);
            }
        }
    }
}

extern "C" void kernel_launch(void* const* d_in, const int* in_sizes, int n_in,
                              void* d_out, int out_size) {
    const float* init_in = (const float*)d_in[0];
    const float* hidden0 = (const float*)d_in[1];
    const float* targets = (const float*)d_in[2];
    const float* W_ih    = (const float*)d_in[3];
    const float* W_hh    = (const float*)d_in[4];
    const float* b_ih    = (const float*)d_in[5];
    const float* b_hh    = (const float*)d_in[6];
    const float* W_out   = (const float*)d_in[7];
    const float* b_out   = (const float*)d_in[8];
    float* out = (float*)d_out;

    cudaFuncSetAttribute(rnn_decoder_kernel,
                         cudaFuncAttributeMaxDynamicSharedMemorySize, SMEM_SZ);
    rnn_decoder_kernel<<<NCTA, NTHR, SMEM_SZ>>>(init_in, hidden0, targets, W_ih,
                                                W_hh, b_ih, b_hh, W_out, b_out,
                                                out);
}